// round 5
// baseline (speedup 1.0000x reference)
#include <cuda_runtime.h>
#include <cstdint>
#include <cstddef>

#define BATCH 8
#define SEQ   2048
#define EMB   1024
#define MTOT  (BATCH * SEQ)

// ---------------- scratch (device globals; no runtime allocation) ----------------
__device__ float g_q[(size_t)MTOT * EMB];          // Q (tf32-rounded)
__device__ float g_k[(size_t)MTOT * EMB];          // K (tf32-rounded)
__device__ float g_v[(size_t)MTOT * EMB];          // Vt [b][e][s] (tf32-rounded)
__device__ float g_p[(size_t)BATCH * SEQ * SEQ];   // scores / probs
__device__ float g_xr[(size_t)MTOT * EMB];         // x rounded to tf32
__device__ float g_wr[(size_t)3 * EMB * EMB];      // Wq,Wk,Wv rounded to tf32

// ---------------- helpers ----------------
__device__ __forceinline__ unsigned f2tf(float f) {
    unsigned u;
    asm("cvt.rna.tf32.f32 %0, %1;" : "=r"(u) : "f"(f));
    return u;
}

__device__ __forceinline__ void mma_tf32(float c[4], const unsigned a[4], const unsigned b[2]) {
    asm volatile(
        "mma.sync.aligned.m16n8k8.row.col.f32.tf32.tf32.f32 "
        "{%0,%1,%2,%3}, {%4,%5,%6,%7}, {%8,%9}, {%0,%1,%2,%3};\n"
        : "+f"(c[0]), "+f"(c[1]), "+f"(c[2]), "+f"(c[3])
        : "r"(a[0]), "r"(a[1]), "r"(a[2]), "r"(a[3]), "r"(b[0]), "r"(b[1]));
}

// XOR swizzle: conflict-free vector loads, <=2-way stores
__device__ __forceinline__ int swz(int lane, int kb) {
    return lane ^ ((lane >> 3) & 3) ^ (kb & 1) ^ ((kb & 2) << 1);
}

// =====================================================================
// HMMA tf32 NT GEMM: C[m,n] = sum_k A[m,k]*B[n,k]
//   CTA tile 128(M) x 256(N), BK=16, 256 thr, 8 warps of 64x64.
//   Fragment-native smem: A-frag = 1 LDS.128, 2 B-frags = 1 LDS.128.
//   MODE 0: proj, C row-major, +bias, round->tf32
//   MODE 1: proj, C -> Vt[b][n][s] transposed, +bias, round->tf32
//   MODE 2: QK^T per batch, *scale, causal tile skip
//   MODE 3: PV per batch, k truncated at diagonal
// =====================================================================
template <int MODE>
__global__ __launch_bounds__(256, 1) void mma_gemm(
    const float* __restrict__ Ag,
    const float* __restrict__ Bg,
    const float* __restrict__ bias,
    float* __restrict__ Cg,
    int M, int N, int K, float scale)
{
    constexpr int BM = 128, BN = 256;
    __shared__ __align__(16) float As[2][2048];   // 8 m-blocks x 2 kb x 32 x 4
    __shared__ __align__(16) float Bs[2][4096];   // 16 n-blocks x 2 kb x 32 x 4

    const int bm = blockIdx.y * BM;
    const int bn = blockIdx.x * BN;
    if (MODE == 2 && 2 * blockIdx.x > blockIdx.y) return;  // fully masked tile

    const int b = (MODE >= 2) ? blockIdx.z : 0;
    const float* A = Ag + (size_t)b * M * K;
    const float* B = Bg + (size_t)b * N * K;

    const int tid  = threadIdx.x;
    const int lane = tid & 31;
    const int wid  = tid >> 5;
    const int gr   = lane >> 2;
    const int gc   = lane & 3;
    const int wm0  = (wid >> 2) * 64;   // warp row origin
    const int wn0  = (wid & 3) * 64;    // warp col origin
    const int mtb  = (wid >> 2) * 4;    // A 16-block base
    const int ntb  = (wid & 3) * 4;     // B 16-block base

    // G2S A: 2 threads per row (8 floats each); B: 1 thread per row (16 floats)
    const int ra = tid >> 1;
    const int kh = tid & 1;

    float acc[4][8][4];
#pragma unroll
    for (int i = 0; i < 4; i++)
#pragma unroll
        for (int j = 0; j < 8; j++)
#pragma unroll
            for (int t = 0; t < 4; t++) acc[i][j][t] = 0.0f;

    const int kend = (MODE == 3) ? (bm + BM) : K;
    const int nch  = kend >> 4;

    float4 pa0, pa1, pb0, pb1, pb2, pb3;  // prefetch regs

    auto ldg = [&](int c) {
        const float* ap = A + (size_t)(bm + ra) * K + (c << 4) + kh * 8;
        pa0 = *(const float4*)(ap);
        pa1 = *(const float4*)(ap + 4);
        const float* bp = B + (size_t)(bn + tid) * K + (c << 4);
        pb0 = *(const float4*)(bp);
        pb1 = *(const float4*)(bp + 4);
        pb2 = *(const float4*)(bp + 8);
        pb3 = *(const float4*)(bp + 12);
    };

    auto sts = [&](int buf) {
        // ---- A: row ra, k = kh*8 + s ----
        {
            float av[8] = {pa0.x, pa0.y, pa0.z, pa0.w, pa1.x, pa1.y, pa1.z, pa1.w};
            const int mt = ra >> 4;
#pragma unroll
            for (int s = 0; s < 8; s++) {
                const int ln = ((ra & 7) << 2) | (s & 3);
                const int sw = swz(ln, kh);
                const int ta = ((ra >> 3) & 1) | (((s >> 2) & 1) << 1);
                As[buf][((((mt << 1) + kh) << 5) + sw) * 4 + ta] = av[s];
            }
        }
        // ---- B: row tid, k = s (0..15) ----
        {
            float bv[16] = {pb0.x, pb0.y, pb0.z, pb0.w, pb1.x, pb1.y, pb1.z, pb1.w,
                            pb2.x, pb2.y, pb2.z, pb2.w, pb3.x, pb3.y, pb3.z, pb3.w};
            const int nt = tid >> 4;
#pragma unroll
            for (int s = 0; s < 16; s++) {
                const int kb = s >> 3;
                const int sl = s & 7;
                const int ln = ((tid & 7) << 2) | (sl & 3);
                const int sw = swz(ln, kb);
                const int tb = ((sl >> 2) & 1) | (((tid >> 3) & 1) << 1);
                Bs[buf][((((nt << 1) + kb) << 5) + sw) * 4 + tb] = bv[s];
            }
        }
    };

    ldg(0);
    sts(0);

    for (int i = 0; i < nch; i++) {
        __syncthreads();                 // buf i&1 ready for all
        if (i + 1 < nch) ldg(i + 1);     // overlap gmem with compute

        const int buf = i & 1;
#pragma unroll
        for (int kb = 0; kb < 2; kb++) {
            const int sw = swz(lane, kb);
            unsigned afr[4][4], bfr[8][2];
#pragma unroll
            for (int mf = 0; mf < 4; mf++) {
                uint4 q = *(const uint4*)&As[buf][(((((mtb + mf) << 1) + kb) << 5) + sw) * 4];
                afr[mf][0] = q.x; afr[mf][1] = q.y; afr[mf][2] = q.z; afr[mf][3] = q.w;
            }
#pragma unroll
            for (int h = 0; h < 4; h++) {
                uint4 q = *(const uint4*)&Bs[buf][(((((ntb + h) << 1) + kb) << 5) + sw) * 4];
                bfr[2 * h][0] = q.x; bfr[2 * h][1] = q.y;
                bfr[2 * h + 1][0] = q.z; bfr[2 * h + 1][1] = q.w;
            }
#pragma unroll
            for (int mf = 0; mf < 4; mf++)
#pragma unroll
                for (int nf = 0; nf < 8; nf++)
                    mma_tf32(acc[mf][nf], afr[mf], bfr[nf]);
        }

        if (i + 1 < nch) sts((i + 1) & 1);   // disjoint from buf being read
    }

    // ---- epilogue ----
#pragma unroll
    for (int mf = 0; mf < 4; mf++) {
#pragma unroll
        for (int nf = 0; nf < 8; nf++) {
            const int row = bm + wm0 + mf * 16 + gr;
            const int col = bn + wn0 + nf * 8 + 2 * gc;
            float* c = acc[mf][nf];

            if (MODE == 0) {
                float bx = bias[col], by = bias[col + 1];
                float2 v0 = make_float2(__uint_as_float(f2tf(c[0] + bx)),
                                        __uint_as_float(f2tf(c[1] + by)));
                float2 v1 = make_float2(__uint_as_float(f2tf(c[2] + bx)),
                                        __uint_as_float(f2tf(c[3] + by)));
                *(float2*)(Cg + (size_t)row * N + col)       = v0;
                *(float2*)(Cg + (size_t)(row + 8) * N + col) = v1;
            } else if (MODE == 1) {
                float bx = bias[col], by = bias[col + 1];
                const int b0 = row >> 11, s0 = row & (SEQ - 1);
                const int b1 = (row + 8) >> 11, s1 = (row + 8) & (SEQ - 1);
                Cg[(size_t)b0 * EMB * SEQ + (size_t)col * SEQ + s0]       = __uint_as_float(f2tf(c[0] + bx));
                Cg[(size_t)b0 * EMB * SEQ + (size_t)(col + 1) * SEQ + s0] = __uint_as_float(f2tf(c[1] + by));
                Cg[(size_t)b1 * EMB * SEQ + (size_t)col * SEQ + s1]       = __uint_as_float(f2tf(c[2] + bx));
                Cg[(size_t)b1 * EMB * SEQ + (size_t)(col + 1) * SEQ + s1] = __uint_as_float(f2tf(c[3] + by));
            } else if (MODE == 2) {
                float* C = Cg + (size_t)b * M * N;
                float2 v0 = make_float2(c[0] * scale, c[1] * scale);
                float2 v1 = make_float2(c[2] * scale, c[3] * scale);
                *(float2*)(C + (size_t)row * N + col)       = v0;
                *(float2*)(C + (size_t)(row + 8) * N + col) = v1;
            } else {
                float* C = Cg + (size_t)b * M * N;
                float2 v0 = make_float2(c[0], c[1]);
                float2 v1 = make_float2(c[2], c[3]);
                *(float2*)(C + (size_t)row * N + col)       = v0;
                *(float2*)(C + (size_t)(row + 8) * N + col) = v1;
            }
        }
    }
}

// =====================================================================
// elementwise tf32-rna rounding
// =====================================================================
__global__ __launch_bounds__(256) void round_tf32(const float* __restrict__ in,
                                                  float* __restrict__ out, int n4)
{
    int i = blockIdx.x * blockDim.x + threadIdx.x;
    if (i < n4) {
        float4 v = ((const float4*)in)[i];
        float4 o;
        o.x = __uint_as_float(f2tf(v.x));
        o.y = __uint_as_float(f2tf(v.y));
        o.z = __uint_as_float(f2tf(v.z));
        o.w = __uint_as_float(f2tf(v.w));
        ((float4*)out)[i] = o;
    }
}

// =====================================================================
// Causal softmax in place. One CTA (256 thr) per row.
// Writes tf32-rounded probs for j<=i, zeros for j>i.
// =====================================================================
__global__ __launch_bounds__(256) void softmax_causal(float* __restrict__ Pg)
{
    const int i = blockIdx.x;
    const int b = blockIdx.y;
    float* row = Pg + ((size_t)b * SEQ + i) * SEQ;
    const int len = i + 1;

    __shared__ float buf[SEQ];
    __shared__ float red[8];
    __shared__ float sval;

    const int tid = threadIdx.x;
    const int lane = tid & 31;
    const int warp = tid >> 5;

    float m = -1e30f;
    for (int j = tid; j < len; j += 256) {
        float v = row[j];
        buf[j] = v;
        m = fmaxf(m, v);
    }
#pragma unroll
    for (int o = 16; o > 0; o >>= 1) m = fmaxf(m, __shfl_xor_sync(0xffffffffu, m, o));
    if (lane == 0) red[warp] = m;
    __syncthreads();
    if (tid == 0) {
        float mm = red[0];
#pragma unroll
        for (int w = 1; w < 8; w++) mm = fmaxf(mm, red[w]);
        sval = mm;
    }
    __syncthreads();
    const float rowmax = sval;
    __syncthreads();

    float s = 0.0f;
    for (int j = tid; j < len; j += 256) {
        float e = __expf(buf[j] - rowmax);
        buf[j] = e;
        s += e;
    }
#pragma unroll
    for (int o = 16; o > 0; o >>= 1) s += __shfl_xor_sync(0xffffffffu, s, o);
    if (lane == 0) red[warp] = s;
    __syncthreads();
    if (tid == 0) {
        float ss = red[0];
#pragma unroll
        for (int w = 1; w < 8; w++) ss += red[w];
        sval = 1.0f / ss;
    }
    __syncthreads();
    const float inv = sval;

    for (int j = tid; j < len; j += 256) row[j] = __uint_as_float(f2tf(buf[j] * inv));
    for (int j = len + tid; j < SEQ; j += 256) row[j] = 0.0f;
}

// =====================================================================
// launch
// =====================================================================
extern "C" void kernel_launch(void* const* d_in, const int* in_sizes, int n_in,
                              void* d_out, int out_size)
{
    const float* x  = (const float*)d_in[0];
    const float* Wq = (const float*)d_in[1];
    const float* bq = (const float*)d_in[2];
    const float* Wk = (const float*)d_in[3];
    const float* bk = (const float*)d_in[4];
    const float* Wv = (const float*)d_in[5];
    const float* bv = (const float*)d_in[6];
    float* out = (float*)d_out;

    float* q;  cudaGetSymbolAddress((void**)&q,  g_q);
    float* k;  cudaGetSymbolAddress((void**)&k,  g_k);
    float* v;  cudaGetSymbolAddress((void**)&v,  g_v);
    float* p;  cudaGetSymbolAddress((void**)&p,  g_p);
    float* xr; cudaGetSymbolAddress((void**)&xr, g_xr);
    float* wr; cudaGetSymbolAddress((void**)&wr, g_wr);

    // 0) pre-round x and weights to tf32 (rna) -> no cvt in GEMM hot loops
    {
        int n4x = MTOT * EMB / 4;
        round_tf32<<<(n4x + 255) / 256, 256>>>(x, xr, n4x);
        int n4w = EMB * EMB / 4;
        round_tf32<<<(n4w + 255) / 256, 256>>>(Wq, wr + (size_t)0 * EMB * EMB, n4w);
        round_tf32<<<(n4w + 255) / 256, 256>>>(Wk, wr + (size_t)1 * EMB * EMB, n4w);
        round_tf32<<<(n4w + 255) / 256, 256>>>(Wv, wr + (size_t)2 * EMB * EMB, n4w);
    }

    // 1) QKV projections (V transposed -> Vt[b][e][s])
    dim3 gProj(EMB / 256, MTOT / 128, 1);
    mma_gemm<0><<<gProj, 256>>>(xr, wr + (size_t)0 * EMB * EMB, bq, q, MTOT, EMB, EMB, 1.0f);
    mma_gemm<0><<<gProj, 256>>>(xr, wr + (size_t)1 * EMB * EMB, bk, k, MTOT, EMB, EMB, 1.0f);
    mma_gemm<1><<<gProj, 256>>>(xr, wr + (size_t)2 * EMB * EMB, bv, v, MTOT, EMB, EMB, 1.0f);

    // 2) scaled QK^T with causal tile skip (garbage above diagonal, never read)
    dim3 gQK(SEQ / 256, SEQ / 128, BATCH);
    mma_gemm<2><<<gQK, 256>>>(q, k, nullptr, p, SEQ, SEQ, EMB, 1.0f / 32.0f);

    // 3) causal softmax (rounds probs to tf32, zeros above diagonal)
    dim3 gSM(SEQ, BATCH, 1);
    softmax_causal<<<gSM, 256>>>(p);

    // 4) PV: O = P * Vt^T, k truncated at diagonal
    dim3 gPV(EMB / 256, SEQ / 128, BATCH);
    mma_gemm<3><<<gPV, 256>>>(p, v, nullptr, out, SEQ, EMB, SEQ, 1.0f);
}

// round 6
// speedup vs baseline: 1.2474x; 1.2474x over previous
#include <cuda_runtime.h>
#include <cstdint>
#include <cstddef>

#define BATCH 8
#define SEQ   2048
#define EMB   1024
#define MTOT  (BATCH * SEQ)

// ---------------- scratch (device globals; no runtime allocation) ----------------
__device__ float g_q[(size_t)MTOT * EMB];          // Q (tf32-rounded)
__device__ float g_k[(size_t)MTOT * EMB];          // K (tf32-rounded)
__device__ float g_v[(size_t)MTOT * EMB];          // Vt [b][e][s] (tf32-rounded)
__device__ float g_p[(size_t)BATCH * SEQ * SEQ];   // scores / probs
__device__ float g_xr[(size_t)MTOT * EMB];         // x rounded to tf32
__device__ float g_wr[(size_t)3 * EMB * EMB];      // Wq,Wk,Wv rounded to tf32

// ---------------- helpers ----------------
__device__ __forceinline__ unsigned f2tf(float f) {
    unsigned u;
    asm("cvt.rna.tf32.f32 %0, %1;" : "=r"(u) : "f"(f));
    return u;
}

__device__ __forceinline__ void mma_tf32(float c[4], const unsigned a[4], const unsigned b[2]) {
    asm volatile(
        "mma.sync.aligned.m16n8k8.row.col.f32.tf32.tf32.f32 "
        "{%0,%1,%2,%3}, {%4,%5,%6,%7}, {%8,%9}, {%0,%1,%2,%3};\n"
        : "+f"(c[0]), "+f"(c[1]), "+f"(c[2]), "+f"(c[3])
        : "r"(a[0]), "r"(a[1]), "r"(a[2]), "r"(a[3]), "r"(b[0]), "r"(b[1]));
}

__device__ __forceinline__ void ldsm4(unsigned r[4], uint32_t addr) {
    asm volatile(
        "ldmatrix.sync.aligned.m8n8.x4.shared.b16 {%0,%1,%2,%3}, [%4];"
        : "=r"(r[0]), "=r"(r[1]), "=r"(r[2]), "=r"(r[3]) : "r"(addr));
}

// tile layout (A and B identical): row r (0..127) of 16 floats, stored as
// 4 chunks of 16B at byte off(r,c) = r*64 + ((c ^ ((r>>1)&3))<<4).
// - STS.128: conflict-free per 8-lane phase
// - LDSM (8 rows, fixed c): even/odd rows split 128B halves, (r>>1)&3 spreads
//   4 rows over 4 chunk slots -> conflict-free
__device__ __forceinline__ int soff(int row, int c) {
    return row * 64 + ((c ^ ((row >> 1) & 3)) << 4);
}

// =====================================================================
// HMMA tf32 NT GEMM: C[m,n] = sum_k A[m,k]*B[n,k]
//   CTA 128x128, BK=16, 256 thr, 8 warps of 64x32. ldmatrix fragment loads.
//   MODE 0: proj, C row-major, +bias, round->tf32
//   MODE 1: proj, C -> Vt[b][n][s] transposed, +bias, round->tf32
//   MODE 2: QK^T per batch, *scale, causal tile skip
//   MODE 3: PV per batch, k truncated at diagonal
// =====================================================================
template <int MODE>
__global__ __launch_bounds__(256, 2) void mma_gemm(
    const float* __restrict__ Ag,
    const float* __restrict__ Bg,
    const float* __restrict__ bias,
    float* __restrict__ Cg,
    int M, int N, int K, float scale)
{
    constexpr int BM = 128;
    __shared__ __align__(16) float As[2][2048];   // 8KB per buffer
    __shared__ __align__(16) float Bs[2][2048];

    const int bm = blockIdx.y * BM;
    const int bn = blockIdx.x * BM;
    if (MODE == 2 && blockIdx.x > blockIdx.y) return;  // fully masked tile

    const int b = (MODE >= 2) ? blockIdx.z : 0;
    const float* A = Ag + (size_t)b * M * K;
    const float* B = Bg + (size_t)b * N * K;

    const int tid  = threadIdx.x;
    const int lane = tid & 31;
    const int wid  = tid >> 5;
    const int gr   = lane >> 2;
    const int gc   = lane & 3;
    const int wm0  = (wid >> 2) * 64;
    const int wn0  = (wid & 3) * 32;

    // G2S: thread -> row tid>>1, k-half tid&1 (A and B identical mapping)
    const int r  = tid >> 1;
    const int kh = tid & 1;
    const int stOff0 = soff(r, 2 * kh);
    const int stOff1 = soff(r, 2 * kh + 1);

    // ldmatrix per-lane byte offsets (within an 8KB buffer)
    // A: matrices q=l>>3: row = wm0 + ((l>>3)&1)*8 + (l&7), c = (l>>4)
    // B: matrices q=l>>3: row = wn0 + ((l>>4)&1)*8 + (l&7), c = (l>>3)&1
    const int rowA = wm0 + ((lane >> 3) & 1) * 8 + (lane & 7);
    const int offA = soff(rowA, lane >> 4);
    const int rowB = wn0 + ((lane >> 4) & 1) * 8 + (lane & 7);
    const int offB = soff(rowB, (lane >> 3) & 1);
    const uint32_t sA = (uint32_t)__cvta_generic_to_shared(&As[0][0]);
    const uint32_t sB = (uint32_t)__cvta_generic_to_shared(&Bs[0][0]);

    float acc[4][4][4];
#pragma unroll
    for (int i = 0; i < 4; i++)
#pragma unroll
        for (int j = 0; j < 4; j++)
#pragma unroll
            for (int t = 0; t < 4; t++) acc[i][j][t] = 0.0f;

    const int kend = (MODE == 3) ? (bm + BM) : K;
    const int nch  = kend >> 4;

    float4 pa0, pa1, pb0, pb1;   // prefetch regs

    auto ldg = [&](int c) {
        const float* ap = A + (size_t)(bm + r) * K + (c << 4) + kh * 8;
        const float* bp = B + (size_t)(bn + r) * K + (c << 4) + kh * 8;
        pa0 = *(const float4*)(ap);
        pa1 = *(const float4*)(ap + 4);
        pb0 = *(const float4*)(bp);
        pb1 = *(const float4*)(bp + 4);
    };

    auto sts = [&](int buf) {
        char* abase = (char*)&As[buf][0];
        char* bbase = (char*)&Bs[buf][0];
        *(float4*)(abase + stOff0) = pa0;
        *(float4*)(abase + stOff1) = pa1;
        *(float4*)(bbase + stOff0) = pb0;
        *(float4*)(bbase + stOff1) = pb1;
    };

    ldg(0);
    sts(0);

    for (int i = 0; i < nch; i++) {
        __syncthreads();                 // buf i&1 ready for all
        if (i + 1 < nch) ldg(i + 1);     // overlap gmem with compute

        const uint32_t aB = sA + (i & 1) * 8192;
        const uint32_t bB = sB + (i & 1) * 8192;
#pragma unroll
        for (int kb = 0; kb < 2; kb++) {
            const int xk = kb << 5;      // kb toggles chunk bit1 -> addr bit5
            unsigned afr[4][4], bq0[4], bq1[4];
#pragma unroll
            for (int mf = 0; mf < 4; mf++)
                ldsm4(afr[mf], aB + (offA ^ xk) + mf * 1024);
            ldsm4(bq0, bB + (offB ^ xk));
            ldsm4(bq1, bB + (offB ^ xk) + 1024);
            unsigned bfr[4][2] = {{bq0[0], bq0[1]}, {bq0[2], bq0[3]},
                                  {bq1[0], bq1[1]}, {bq1[2], bq1[3]}};
#pragma unroll
            for (int mf = 0; mf < 4; mf++)
#pragma unroll
                for (int nf = 0; nf < 4; nf++)
                    mma_tf32(acc[mf][nf], afr[mf], bfr[nf]);
        }

        if (i + 1 < nch) sts((i + 1) & 1);   // disjoint from buf being read
    }

    // ---- epilogue ----
#pragma unroll
    for (int mf = 0; mf < 4; mf++) {
#pragma unroll
        for (int nf = 0; nf < 4; nf++) {
            const int row = bm + wm0 + mf * 16 + gr;
            const int col = bn + wn0 + nf * 8 + 2 * gc;
            float* c = acc[mf][nf];

            if (MODE == 0) {
                float bx = bias[col], by = bias[col + 1];
                float2 v0 = make_float2(__uint_as_float(f2tf(c[0] + bx)),
                                        __uint_as_float(f2tf(c[1] + by)));
                float2 v1 = make_float2(__uint_as_float(f2tf(c[2] + bx)),
                                        __uint_as_float(f2tf(c[3] + by)));
                *(float2*)(Cg + (size_t)row * N + col)       = v0;
                *(float2*)(Cg + (size_t)(row + 8) * N + col) = v1;
            } else if (MODE == 1) {
                float bx = bias[col], by = bias[col + 1];
                const int b0 = row >> 11, s0 = row & (SEQ - 1);
                const int b1 = (row + 8) >> 11, s1 = (row + 8) & (SEQ - 1);
                Cg[(size_t)b0 * EMB * SEQ + (size_t)col * SEQ + s0]       = __uint_as_float(f2tf(c[0] + bx));
                Cg[(size_t)b0 * EMB * SEQ + (size_t)(col + 1) * SEQ + s0] = __uint_as_float(f2tf(c[1] + by));
                Cg[(size_t)b1 * EMB * SEQ + (size_t)col * SEQ + s1]       = __uint_as_float(f2tf(c[2] + bx));
                Cg[(size_t)b1 * EMB * SEQ + (size_t)(col + 1) * SEQ + s1] = __uint_as_float(f2tf(c[3] + by));
            } else if (MODE == 2) {
                float* C = Cg + (size_t)b * M * N;
                float2 v0 = make_float2(c[0] * scale, c[1] * scale);
                float2 v1 = make_float2(c[2] * scale, c[3] * scale);
                *(float2*)(C + (size_t)row * N + col)       = v0;
                *(float2*)(C + (size_t)(row + 8) * N + col) = v1;
            } else {
                float* C = Cg + (size_t)b * M * N;
                float2 v0 = make_float2(c[0], c[1]);
                float2 v1 = make_float2(c[2], c[3]);
                *(float2*)(C + (size_t)row * N + col)       = v0;
                *(float2*)(C + (size_t)(row + 8) * N + col) = v1;
            }
        }
    }
}

// =====================================================================
// elementwise tf32-rna rounding
// =====================================================================
__global__ __launch_bounds__(256) void round_tf32(const float* __restrict__ in,
                                                  float* __restrict__ out, int n4)
{
    int i = blockIdx.x * blockDim.x + threadIdx.x;
    if (i < n4) {
        float4 v = ((const float4*)in)[i];
        float4 o;
        o.x = __uint_as_float(f2tf(v.x));
        o.y = __uint_as_float(f2tf(v.y));
        o.z = __uint_as_float(f2tf(v.z));
        o.w = __uint_as_float(f2tf(v.w));
        ((float4*)out)[i] = o;
    }
}

// =====================================================================
// Causal softmax in place. One CTA (256 thr) per row.
// Writes tf32-rounded probs for j<=i, zeros for j>i.
// =====================================================================
__global__ __launch_bounds__(256) void softmax_causal(float* __restrict__ Pg)
{
    const int i = blockIdx.x;
    const int b = blockIdx.y;
    float* row = Pg + ((size_t)b * SEQ + i) * SEQ;
    const int len = i + 1;

    __shared__ float buf[SEQ];
    __shared__ float red[8];
    __shared__ float sval;

    const int tid = threadIdx.x;
    const int lane = tid & 31;
    const int warp = tid >> 5;

    float m = -1e30f;
    for (int j = tid; j < len; j += 256) {
        float v = row[j];
        buf[j] = v;
        m = fmaxf(m, v);
    }
#pragma unroll
    for (int o = 16; o > 0; o >>= 1) m = fmaxf(m, __shfl_xor_sync(0xffffffffu, m, o));
    if (lane == 0) red[warp] = m;
    __syncthreads();
    if (tid == 0) {
        float mm = red[0];
#pragma unroll
        for (int w = 1; w < 8; w++) mm = fmaxf(mm, red[w]);
        sval = mm;
    }
    __syncthreads();
    const float rowmax = sval;
    __syncthreads();

    float s = 0.0f;
    for (int j = tid; j < len; j += 256) {
        float e = __expf(buf[j] - rowmax);
        buf[j] = e;
        s += e;
    }
#pragma unroll
    for (int o = 16; o > 0; o >>= 1) s += __shfl_xor_sync(0xffffffffu, s, o);
    if (lane == 0) red[warp] = s;
    __syncthreads();
    if (tid == 0) {
        float ss = red[0];
#pragma unroll
        for (int w = 1; w < 8; w++) ss += red[w];
        sval = 1.0f / ss;
    }
    __syncthreads();
    const float inv = sval;

    for (int j = tid; j < len; j += 256) row[j] = __uint_as_float(f2tf(buf[j] * inv));
    for (int j = len + tid; j < SEQ; j += 256) row[j] = 0.0f;
}

// =====================================================================
// launch
// =====================================================================
extern "C" void kernel_launch(void* const* d_in, const int* in_sizes, int n_in,
                              void* d_out, int out_size)
{
    const float* x  = (const float*)d_in[0];
    const float* Wq = (const float*)d_in[1];
    const float* bq = (const float*)d_in[2];
    const float* Wk = (const float*)d_in[3];
    const float* bk = (const float*)d_in[4];
    const float* Wv = (const float*)d_in[5];
    const float* bv = (const float*)d_in[6];
    float* out = (float*)d_out;

    float* q;  cudaGetSymbolAddress((void**)&q,  g_q);
    float* k;  cudaGetSymbolAddress((void**)&k,  g_k);
    float* v;  cudaGetSymbolAddress((void**)&v,  g_v);
    float* p;  cudaGetSymbolAddress((void**)&p,  g_p);
    float* xr; cudaGetSymbolAddress((void**)&xr, g_xr);
    float* wr; cudaGetSymbolAddress((void**)&wr, g_wr);

    // 0) pre-round x and weights to tf32 (rna) -> no cvt in GEMM hot loops
    {
        int n4x = MTOT * EMB / 4;
        round_tf32<<<(n4x + 255) / 256, 256>>>(x, xr, n4x);
        int n4w = EMB * EMB / 4;
        round_tf32<<<(n4w + 255) / 256, 256>>>(Wq, wr + (size_t)0 * EMB * EMB, n4w);
        round_tf32<<<(n4w + 255) / 256, 256>>>(Wk, wr + (size_t)1 * EMB * EMB, n4w);
        round_tf32<<<(n4w + 255) / 256, 256>>>(Wv, wr + (size_t)2 * EMB * EMB, n4w);
    }

    // 1) QKV projections (V transposed -> Vt[b][e][s])
    dim3 gProj(EMB / 128, MTOT / 128, 1);
    mma_gemm<0><<<gProj, 256>>>(xr, wr + (size_t)0 * EMB * EMB, bq, q, MTOT, EMB, EMB, 1.0f);
    mma_gemm<0><<<gProj, 256>>>(xr, wr + (size_t)1 * EMB * EMB, bk, k, MTOT, EMB, EMB, 1.0f);
    mma_gemm<1><<<gProj, 256>>>(xr, wr + (size_t)2 * EMB * EMB, bv, v, MTOT, EMB, EMB, 1.0f);

    // 2) scaled QK^T with causal tile skip (garbage above diagonal, never read)
    dim3 gQK(SEQ / 128, SEQ / 128, BATCH);
    mma_gemm<2><<<gQK, 256>>>(q, k, nullptr, p, SEQ, SEQ, EMB, 1.0f / 32.0f);

    // 3) causal softmax (rounds probs to tf32, zeros above diagonal)
    dim3 gSM(SEQ, BATCH, 1);
    softmax_causal<<<gSM, 256>>>(p);

    // 4) PV: O = P * Vt^T, k truncated at diagonal
    dim3 gPV(EMB / 128, SEQ / 128, BATCH);
    mma_gemm<3><<<gPV, 256>>>(p, v, nullptr, out, SEQ, EMB, SEQ, 1.0f);
}

// round 7
// speedup vs baseline: 1.5773x; 1.2645x over previous
#include <cuda_runtime.h>
#include <cstdint>
#include <cstddef>

#define BATCH 8
#define SEQ   2048
#define EMB   1024
#define MTOT  (BATCH * SEQ)

// ---------------- scratch (device globals; no runtime allocation) ----------------
__device__ float g_q[(size_t)MTOT * EMB];          // Q (tf32-rounded)
__device__ float g_k[(size_t)MTOT * EMB];          // K (tf32-rounded)
__device__ float g_v[(size_t)MTOT * EMB];          // Vt [b][e][s] (tf32-rounded)
__device__ float g_p[(size_t)BATCH * SEQ * SEQ];   // scores / probs
__device__ float g_xr[(size_t)MTOT * EMB];         // x rounded to tf32
__device__ float g_wr[(size_t)3 * EMB * EMB];      // Wq,Wk,Wv rounded to tf32

// ---------------- helpers ----------------
__device__ __forceinline__ unsigned f2tf(float f) {
    unsigned u;
    asm("cvt.rna.tf32.f32 %0, %1;" : "=r"(u) : "f"(f));
    return u;
}

__device__ __forceinline__ void mma_tf32(float c[4], const unsigned a[4], const unsigned b[2]) {
    asm volatile(
        "mma.sync.aligned.m16n8k8.row.col.f32.tf32.tf32.f32 "
        "{%0,%1,%2,%3}, {%4,%5,%6,%7}, {%8,%9}, {%0,%1,%2,%3};\n"
        : "+f"(c[0]), "+f"(c[1]), "+f"(c[2]), "+f"(c[3])
        : "r"(a[0]), "r"(a[1]), "r"(a[2]), "r"(a[3]), "r"(b[0]), "r"(b[1]));
}

__device__ __forceinline__ void ldsm4(unsigned r[4], uint32_t addr) {
    asm volatile(
        "ldmatrix.sync.aligned.m8n8.x4.shared.b16 {%0,%1,%2,%3}, [%4];"
        : "=r"(r[0]), "=r"(r[1]), "=r"(r[2]), "=r"(r[3]) : "r"(addr));
}

__device__ __forceinline__ void cpa16(uint32_t s, const void* g) {
    asm volatile("cp.async.cg.shared.global [%0], [%1], 16;" :: "r"(s), "l"(g));
}
__device__ __forceinline__ void cpa_commit() { asm volatile("cp.async.commit_group;" ::: "memory"); }
__device__ __forceinline__ void cpa_wait1()  { asm volatile("cp.async.wait_group 1;" ::: "memory"); }
__device__ __forceinline__ void cpa_wait0()  { asm volatile("cp.async.wait_group 0;" ::: "memory"); }

// tile layout (A and B identical): row r (0..127) of 16 floats, stored as
// 4 chunks of 16B at byte off(r,c) = r*64 + ((c ^ ((r>>1)&3))<<4).
__device__ __forceinline__ int soff(int row, int c) {
    return row * 64 + ((c ^ ((row >> 1) & 3)) << 4);
}

// =====================================================================
// HMMA tf32 NT GEMM: C[m,n] = sum_k A[m,k]*B[n,k]
//   CTA 128x128, BK=16, 256 thr, 8 warps of 64x32.
//   3-stage cp.async pipeline; ldmatrix fragment loads.
//   MODE 0: proj, C row-major, +bias, round->tf32
//   MODE 1: proj, C -> Vt[b][n][s] transposed, +bias, round->tf32
//   MODE 2: QK^T per batch, *scale, causal tile skip
//   MODE 3: PV per batch, k truncated at diagonal
// =====================================================================
template <int MODE>
__global__ __launch_bounds__(256, 2) void mma_gemm(
    const float* __restrict__ Ag,
    const float* __restrict__ Bg,
    const float* __restrict__ bias,
    float* __restrict__ Cg,
    int M, int N, int K, float scale)
{
    constexpr int BM = 128;
    __shared__ __align__(16) float As[3][2048];   // 8KB per stage
    __shared__ __align__(16) float Bs[3][2048];

    const int bm = blockIdx.y * BM;
    const int bn = blockIdx.x * BM;
    if (MODE == 2 && blockIdx.x > blockIdx.y) return;  // fully masked tile

    const int b = (MODE >= 2) ? blockIdx.z : 0;
    const float* A = Ag + (size_t)b * M * K;
    const float* B = Bg + (size_t)b * N * K;

    const int tid  = threadIdx.x;
    const int lane = tid & 31;
    const int wid  = tid >> 5;
    const int gr   = lane >> 2;
    const int gc   = lane & 3;
    const int wm0  = (wid >> 2) * 64;
    const int wn0  = (wid & 3) * 32;

    // G2S: thread -> row tid>>1, k-half tid&1 (A and B identical mapping)
    const int r  = tid >> 1;
    const int kh = tid & 1;
    const int stOff0 = soff(r, 2 * kh);
    const int stOff1 = soff(r, 2 * kh + 1);

    // ldmatrix per-lane byte offsets (within an 8KB stage)
    const int rowA = wm0 + ((lane >> 3) & 1) * 8 + (lane & 7);
    const int offA = soff(rowA, lane >> 4);
    const int rowB = wn0 + ((lane >> 4) & 1) * 8 + (lane & 7);
    const int offB = soff(rowB, (lane >> 3) & 1);
    const uint32_t sA = (uint32_t)__cvta_generic_to_shared(&As[0][0]);
    const uint32_t sB = (uint32_t)__cvta_generic_to_shared(&Bs[0][0]);

    float acc[4][4][4];
#pragma unroll
    for (int i = 0; i < 4; i++)
#pragma unroll
        for (int j = 0; j < 4; j++)
#pragma unroll
            for (int t = 0; t < 4; t++) acc[i][j][t] = 0.0f;

    const int kend = (MODE == 3) ? (bm + BM) : K;
    const int nch  = kend >> 4;

    auto fill = [&](int c) {                      // stage c%3 <- chunk c
        const uint32_t aB = sA + (uint32_t)(c % 3) * 8192;
        const uint32_t bB = sB + (uint32_t)(c % 3) * 8192;
        const float* ap = A + (size_t)(bm + r) * K + (c << 4) + kh * 8;
        const float* bp = B + (size_t)(bn + r) * K + (c << 4) + kh * 8;
        cpa16(aB + stOff0, ap);
        cpa16(aB + stOff1, ap + 4);
        cpa16(bB + stOff0, bp);
        cpa16(bB + stOff1, bp + 4);
        cpa_commit();
    };

    fill(0);
    if (nch > 1) fill(1); else cpa_commit();

    for (int i = 0; i < nch; i++) {
        cpa_wait1();                 // chunk i landed (<=1 group pending)
        __syncthreads();             // visible to all; also fences reuse of stage (i-1)%3

        const uint32_t aB = sA + (uint32_t)(i % 3) * 8192;
        const uint32_t bB = sB + (uint32_t)(i % 3) * 8192;
#pragma unroll
        for (int kb = 0; kb < 2; kb++) {
            const int xk = kb << 5;
            unsigned afr[4][4], bq0[4], bq1[4];
#pragma unroll
            for (int mf = 0; mf < 4; mf++)
                ldsm4(afr[mf], aB + (offA ^ xk) + mf * 1024);
            ldsm4(bq0, bB + (offB ^ xk));
            ldsm4(bq1, bB + (offB ^ xk) + 1024);
            unsigned bfr[4][2] = {{bq0[0], bq0[1]}, {bq0[2], bq0[3]},
                                  {bq1[0], bq1[1]}, {bq1[2], bq1[3]}};
#pragma unroll
            for (int mf = 0; mf < 4; mf++)
#pragma unroll
                for (int nf = 0; nf < 4; nf++)
                    mma_tf32(acc[mf][nf], afr[mf], bfr[nf]);
        }

        if (i + 2 < nch) fill(i + 2);   // stage (i+2)%3 == (i-1)%3, freed by the sync above
        else cpa_commit();              // keep group counts consistent
    }
    cpa_wait0();

    // ---- epilogue ----
#pragma unroll
    for (int mf = 0; mf < 4; mf++) {
#pragma unroll
        for (int nf = 0; nf < 4; nf++) {
            const int row = bm + wm0 + mf * 16 + gr;
            const int col = bn + wn0 + nf * 8 + 2 * gc;
            float* c = acc[mf][nf];

            if (MODE == 0) {
                float bx = bias[col], by = bias[col + 1];
                float2 v0 = make_float2(__uint_as_float(f2tf(c[0] + bx)),
                                        __uint_as_float(f2tf(c[1] + by)));
                float2 v1 = make_float2(__uint_as_float(f2tf(c[2] + bx)),
                                        __uint_as_float(f2tf(c[3] + by)));
                *(float2*)(Cg + (size_t)row * N + col)       = v0;
                *(float2*)(Cg + (size_t)(row + 8) * N + col) = v1;
            } else if (MODE == 1) {
                float bx = bias[col], by = bias[col + 1];
                const int b0 = row >> 11, s0 = row & (SEQ - 1);
                const int b1 = (row + 8) >> 11, s1 = (row + 8) & (SEQ - 1);
                Cg[(size_t)b0 * EMB * SEQ + (size_t)col * SEQ + s0]       = __uint_as_float(f2tf(c[0] + bx));
                Cg[(size_t)b0 * EMB * SEQ + (size_t)(col + 1) * SEQ + s0] = __uint_as_float(f2tf(c[1] + by));
                Cg[(size_t)b1 * EMB * SEQ + (size_t)col * SEQ + s1]       = __uint_as_float(f2tf(c[2] + bx));
                Cg[(size_t)b1 * EMB * SEQ + (size_t)(col + 1) * SEQ + s1] = __uint_as_float(f2tf(c[3] + by));
            } else if (MODE == 2) {
                float* C = Cg + (size_t)b * M * N;
                float2 v0 = make_float2(c[0] * scale, c[1] * scale);
                float2 v1 = make_float2(c[2] * scale, c[3] * scale);
                *(float2*)(C + (size_t)row * N + col)       = v0;
                *(float2*)(C + (size_t)(row + 8) * N + col) = v1;
            } else {
                float* C = Cg + (size_t)b * M * N;
                float2 v0 = make_float2(c[0], c[1]);
                float2 v1 = make_float2(c[2], c[3]);
                *(float2*)(C + (size_t)row * N + col)       = v0;
                *(float2*)(C + (size_t)(row + 8) * N + col) = v1;
            }
        }
    }
}

// =====================================================================
// elementwise tf32-rna rounding
// =====================================================================
__global__ __launch_bounds__(256) void round_tf32(const float* __restrict__ in,
                                                  float* __restrict__ out, int n4)
{
    int i = blockIdx.x * blockDim.x + threadIdx.x;
    if (i < n4) {
        float4 v = ((const float4*)in)[i];
        float4 o;
        o.x = __uint_as_float(f2tf(v.x));
        o.y = __uint_as_float(f2tf(v.y));
        o.z = __uint_as_float(f2tf(v.z));
        o.w = __uint_as_float(f2tf(v.w));
        ((float4*)out)[i] = o;
    }
}

// =====================================================================
// Causal softmax in place. One CTA (256 thr) per row; float4 main loops.
// Writes tf32-rounded probs for j<=i, zeros for j>i.
// =====================================================================
__global__ __launch_bounds__(256) void softmax_causal(float* __restrict__ Pg)
{
    const int i = blockIdx.x;
    const int b = blockIdx.y;
    float* row = Pg + ((size_t)b * SEQ + i) * SEQ;
    const int len = i + 1;
    const int len4 = len >> 2;          // full float4 groups

    __shared__ __align__(16) float buf[SEQ];
    __shared__ float red[8];
    __shared__ float sval;

    const int tid = threadIdx.x;
    const int lane = tid & 31;
    const int warp = tid >> 5;

    // ---- pass 1: load + max (vectorized) ----
    float m = -1e30f;
    for (int j4 = tid; j4 < len4; j4 += 256) {
        float4 v = ((const float4*)row)[j4];
        ((float4*)buf)[j4] = v;
        m = fmaxf(fmaxf(fmaxf(m, v.x), fmaxf(v.y, v.z)), v.w);
    }
    for (int j = len4 * 4 + tid; j < len; j += 256) {
        float v = row[j];
        buf[j] = v;
        m = fmaxf(m, v);
    }
#pragma unroll
    for (int o = 16; o > 0; o >>= 1) m = fmaxf(m, __shfl_xor_sync(0xffffffffu, m, o));
    if (lane == 0) red[warp] = m;
    __syncthreads();
    if (tid == 0) {
        float mm = red[0];
#pragma unroll
        for (int w = 1; w < 8; w++) mm = fmaxf(mm, red[w]);
        sval = mm;
    }
    __syncthreads();
    const float rowmax = sval;
    __syncthreads();

    // ---- pass 2: exp + sum ----
    float s = 0.0f;
    for (int j4 = tid; j4 < len4; j4 += 256) {
        float4 v = ((const float4*)buf)[j4];
        v.x = __expf(v.x - rowmax);
        v.y = __expf(v.y - rowmax);
        v.z = __expf(v.z - rowmax);
        v.w = __expf(v.w - rowmax);
        ((float4*)buf)[j4] = v;
        s += v.x + v.y + v.z + v.w;
    }
    for (int j = len4 * 4 + tid; j < len; j += 256) {
        float e = __expf(buf[j] - rowmax);
        buf[j] = e;
        s += e;
    }
#pragma unroll
    for (int o = 16; o > 0; o >>= 1) s += __shfl_xor_sync(0xffffffffu, s, o);
    if (lane == 0) red[warp] = s;
    __syncthreads();
    if (tid == 0) {
        float ss = red[0];
#pragma unroll
        for (int w = 1; w < 8; w++) ss += red[w];
        sval = 1.0f / ss;
    }
    __syncthreads();
    const float inv = sval;

    // ---- pass 3: write normalized (tf32-rounded) + zero tail ----
    for (int j4 = tid; j4 < len4; j4 += 256) {
        float4 v = ((const float4*)buf)[j4];
        v.x = __uint_as_float(f2tf(v.x * inv));
        v.y = __uint_as_float(f2tf(v.y * inv));
        v.z = __uint_as_float(f2tf(v.z * inv));
        v.w = __uint_as_float(f2tf(v.w * inv));
        ((float4*)row)[j4] = v;
    }
    for (int j = len4 * 4 + tid; j < len; j += 256)
        row[j] = __uint_as_float(f2tf(buf[j] * inv));
    for (int j = len + tid; j < SEQ; j += 256) row[j] = 0.0f;
}

// =====================================================================
// launch
// =====================================================================
extern "C" void kernel_launch(void* const* d_in, const int* in_sizes, int n_in,
                              void* d_out, int out_size)
{
    const float* x  = (const float*)d_in[0];
    const float* Wq = (const float*)d_in[1];
    const float* bq = (const float*)d_in[2];
    const float* Wk = (const float*)d_in[3];
    const float* bk = (const float*)d_in[4];
    const float* Wv = (const float*)d_in[5];
    const float* bv = (const float*)d_in[6];
    float* out = (float*)d_out;

    float* q;  cudaGetSymbolAddress((void**)&q,  g_q);
    float* k;  cudaGetSymbolAddress((void**)&k,  g_k);
    float* v;  cudaGetSymbolAddress((void**)&v,  g_v);
    float* p;  cudaGetSymbolAddress((void**)&p,  g_p);
    float* xr; cudaGetSymbolAddress((void**)&xr, g_xr);
    float* wr; cudaGetSymbolAddress((void**)&wr, g_wr);

    // 0) pre-round x and weights to tf32 (rna) -> no cvt in GEMM hot loops
    {
        int n4x = MTOT * EMB / 4;
        round_tf32<<<(n4x + 255) / 256, 256>>>(x, xr, n4x);
        int n4w = EMB * EMB / 4;
        round_tf32<<<(n4w + 255) / 256, 256>>>(Wq, wr + (size_t)0 * EMB * EMB, n4w);
        round_tf32<<<(n4w + 255) / 256, 256>>>(Wk, wr + (size_t)1 * EMB * EMB, n4w);
        round_tf32<<<(n4w + 255) / 256, 256>>>(Wv, wr + (size_t)2 * EMB * EMB, n4w);
    }

    // 1) QKV projections (V transposed -> Vt[b][e][s])
    dim3 gProj(EMB / 128, MTOT / 128, 1);
    mma_gemm<0><<<gProj, 256>>>(xr, wr + (size_t)0 * EMB * EMB, bq, q, MTOT, EMB, EMB, 1.0f);
    mma_gemm<0><<<gProj, 256>>>(xr, wr + (size_t)1 * EMB * EMB, bk, k, MTOT, EMB, EMB, 1.0f);
    mma_gemm<1><<<gProj, 256>>>(xr, wr + (size_t)2 * EMB * EMB, bv, v, MTOT, EMB, EMB, 1.0f);

    // 2) scaled QK^T with causal tile skip (garbage above diagonal, never read)
    dim3 gQK(SEQ / 128, SEQ / 128, BATCH);
    mma_gemm<2><<<gQK, 256>>>(q, k, nullptr, p, SEQ, SEQ, EMB, 1.0f / 32.0f);

    // 3) causal softmax (rounds probs to tf32, zeros above diagonal)
    dim3 gSM(SEQ, BATCH, 1);
    softmax_causal<<<gSM, 256>>>(p);

    // 4) PV: O = P * Vt^T, k truncated at diagonal
    dim3 gPV(EMB / 128, SEQ / 128, BATCH);
    mma_gemm<3><<<gPV, 256>>>(p, v, nullptr, out, SEQ, EMB, SEQ, 1.0f);
}

// round 9
// speedup vs baseline: 2.4883x; 1.5776x over previous
#include <cuda_runtime.h>
#include <cuda_fp16.h>
#include <cstdint>
#include <cstddef>

#define BATCH 8
#define SEQ   2048
#define EMB   1024
#define MTOT  (BATCH * SEQ)

// ---------------- scratch (device globals; no runtime allocation) ----------------
__device__ __half g_q[(size_t)MTOT * EMB];           // Q (fp16)
__device__ __half g_k[(size_t)MTOT * EMB];           // K (fp16)
__device__ __half g_v[(size_t)MTOT * EMB];           // Vt [b][e][s] (fp16)
__device__ float  g_p[(size_t)BATCH * SEQ * SEQ];    // QK^T scores (fp32)
__device__ __half g_ph[(size_t)BATCH * SEQ * SEQ];   // softmax probs (fp16)
__device__ __half g_xh[(size_t)MTOT * EMB];          // x -> fp16
__device__ __half g_wh[(size_t)3 * EMB * EMB];       // Wq,Wk,Wv -> fp16

// ---------------- helpers ----------------
__device__ __forceinline__ void mma_f16(float c[4], const unsigned a[4], const unsigned b[2]) {
    asm volatile(
        "mma.sync.aligned.m16n8k16.row.col.f32.f16.f16.f32 "
        "{%0,%1,%2,%3}, {%4,%5,%6,%7}, {%8,%9}, {%0,%1,%2,%3};\n"
        : "+f"(c[0]), "+f"(c[1]), "+f"(c[2]), "+f"(c[3])
        : "r"(a[0]), "r"(a[1]), "r"(a[2]), "r"(a[3]), "r"(b[0]), "r"(b[1]));
}

__device__ __forceinline__ void ldsm4(unsigned r[4], uint32_t addr) {
    asm volatile(
        "ldmatrix.sync.aligned.m8n8.x4.shared.b16 {%0,%1,%2,%3}, [%4];"
        : "=r"(r[0]), "=r"(r[1]), "=r"(r[2]), "=r"(r[3]) : "r"(addr));
}

__device__ __forceinline__ void cpa16(uint32_t s, const void* g) {
    asm volatile("cp.async.cg.shared.global [%0], [%1], 16;" :: "r"(s), "l"(g));
}
__device__ __forceinline__ void cpa_commit() { asm volatile("cp.async.commit_group;" ::: "memory"); }
__device__ __forceinline__ void cpa_wait1()  { asm volatile("cp.async.wait_group 1;" ::: "memory"); }
__device__ __forceinline__ void cpa_wait0()  { asm volatile("cp.async.wait_group 0;" ::: "memory"); }

// fp16 tile: row r (0..127) of 16 halves (32B) = 2 chunks of 16B.
// phys byte off(r,c) = (r>>2)*128 + ((((r&3)<<1)|c) ^ ((r>>2)&1))*16
// -> LDSM 8-lane phases and cp.async stores both conflict-free.
__device__ __forceinline__ int soff16(int r, int c) {
    return (r >> 2) * 128 + (((((r & 3) << 1) | c) ^ ((r >> 2) & 1)) << 4);
}

// =====================================================================
// HMMA fp16 NT GEMM: C[m,n] = sum_k A[m,k]*B[n,k]   (A,B fp16; acc fp32)
//   CTA 128x128, BK=16, 256 thr, 8 warps of 64x32.
//   3-stage cp.async pipeline; ldmatrix x4 fragment loads.
//   MODE 0: proj, C fp16 row-major, +bias
//   MODE 1: proj, C fp16 -> Vt[b][n][s] transposed, +bias
//   MODE 2: QK^T per batch, C fp32, *scale, causal tile skip
//   MODE 3: PV per batch, C fp32, k truncated at diagonal
// =====================================================================
template <int MODE>
__global__ __launch_bounds__(256, 2) void mma_gemm(
    const __half* __restrict__ Ag,
    const __half* __restrict__ Bg,
    const float* __restrict__ bias,
    void* __restrict__ Cout,
    int M, int N, int K, float scale)
{
    constexpr int BM = 128;
    __shared__ __align__(16) __half As[3][2048];   // 4KB per stage
    __shared__ __align__(16) __half Bs[3][2048];

    const int bm = blockIdx.y * BM;
    const int bn = blockIdx.x * BM;
    if (MODE == 2 && blockIdx.x > blockIdx.y) return;  // fully masked tile

    const int b = (MODE >= 2) ? blockIdx.z : 0;
    const __half* A = Ag + (size_t)b * M * K;
    const __half* B = Bg + (size_t)b * N * K;

    const int tid  = threadIdx.x;
    const int lane = tid & 31;
    const int wid  = tid >> 5;
    const int gr   = lane >> 2;
    const int gc   = lane & 3;
    const int wm0  = (wid >> 2) * 64;
    const int wn0  = (wid & 3) * 32;

    // G2S: thread -> row tid>>1, chunk tid&1 (A and B identical mapping)
    const int r  = tid >> 1;
    const int cc = tid & 1;
    const int stOff = soff16(r, cc);

    // LDSM per-lane offsets: rowLoc = ((l>>3)&1)*8 + (l&7), chunk = l>>4
    const int rowLoc = ((lane >> 3) & 1) * 8 + (lane & 7);
    const int cfr    = lane >> 4;
    const int offA = soff16(wm0 + rowLoc, cfr);   // + mf*512 per 16-row block
    const int offB = soff16(wn0 + rowLoc, cfr);   // + h*512 per 16-n block
    const uint32_t sA = (uint32_t)__cvta_generic_to_shared(&As[0][0]);
    const uint32_t sB = (uint32_t)__cvta_generic_to_shared(&Bs[0][0]);

    float acc[4][4][4];
#pragma unroll
    for (int i = 0; i < 4; i++)
#pragma unroll
        for (int j = 0; j < 4; j++)
#pragma unroll
            for (int t = 0; t < 4; t++) acc[i][j][t] = 0.0f;

    const int kend = (MODE == 3) ? (bm + BM) : K;
    const int nch  = kend >> 4;

    auto fill = [&](int c) {                      // stage c%3 <- chunk c (k = 16c..16c+15)
        const uint32_t aB = sA + (uint32_t)(c % 3) * 4096;
        const uint32_t bB = sB + (uint32_t)(c % 3) * 4096;
        cpa16(aB + stOff, A + (size_t)(bm + r) * K + (c << 4) + cc * 8);
        cpa16(bB + stOff, B + (size_t)(bn + r) * K + (c << 4) + cc * 8);
        cpa_commit();
    };

    fill(0);
    if (nch > 1) fill(1); else cpa_commit();

    for (int i = 0; i < nch; i++) {
        cpa_wait1();                 // chunk i landed (<=1 group pending)
        __syncthreads();             // visible to all; fences reuse of stage (i-1)%3

        const uint32_t aB = sA + (uint32_t)(i % 3) * 4096;
        const uint32_t bB = sB + (uint32_t)(i % 3) * 4096;

        unsigned afr[4][4];
#pragma unroll
        for (int mf = 0; mf < 4; mf++)
            ldsm4(afr[mf], aB + offA + mf * 512);
        unsigned bq0[4], bq1[4];
        ldsm4(bq0, bB + offB);
        ldsm4(bq1, bB + offB + 512);
        // x4 over 16 n-rows: regs = {b0(nf), b0(nf+1), b1(nf), b1(nf+1)}
        unsigned bfr[4][2] = {{bq0[0], bq0[2]}, {bq0[1], bq0[3]},
                              {bq1[0], bq1[2]}, {bq1[1], bq1[3]}};
#pragma unroll
        for (int mf = 0; mf < 4; mf++)
#pragma unroll
            for (int nf = 0; nf < 4; nf++)
                mma_f16(acc[mf][nf], afr[mf], bfr[nf]);

        if (i + 2 < nch) fill(i + 2);   // stage (i+2)%3 == (i-1)%3, freed by the sync
        else cpa_commit();              // keep group counts consistent
    }
    cpa_wait0();

    // ---- epilogue ----
#pragma unroll
    for (int mf = 0; mf < 4; mf++) {
#pragma unroll
        for (int nf = 0; nf < 4; nf++) {
            const int row = bm + wm0 + mf * 16 + gr;
            const int col = bn + wn0 + nf * 8 + 2 * gc;
            float* c = acc[mf][nf];

            if (MODE == 0) {
                __half* Cg = (__half*)Cout;
                float bx = bias[col], by = bias[col + 1];
                *(__half2*)(Cg + (size_t)row * N + col)       = __floats2half2_rn(c[0] + bx, c[1] + by);
                *(__half2*)(Cg + (size_t)(row + 8) * N + col) = __floats2half2_rn(c[2] + bx, c[3] + by);
            } else if (MODE == 1) {
                __half* Cg = (__half*)Cout;
                float bx = bias[col], by = bias[col + 1];
                const int b0 = row >> 11, s0 = row & (SEQ - 1);
                const int b1 = (row + 8) >> 11, s1 = (row + 8) & (SEQ - 1);
                Cg[(size_t)b0 * EMB * SEQ + (size_t)col * SEQ + s0]       = __float2half_rn(c[0] + bx);
                Cg[(size_t)b0 * EMB * SEQ + (size_t)(col + 1) * SEQ + s0] = __float2half_rn(c[1] + by);
                Cg[(size_t)b1 * EMB * SEQ + (size_t)col * SEQ + s1]       = __float2half_rn(c[2] + bx);
                Cg[(size_t)b1 * EMB * SEQ + (size_t)(col + 1) * SEQ + s1] = __float2half_rn(c[3] + by);
            } else if (MODE == 2) {
                float* Cg = (float*)Cout + (size_t)b * M * N;
                *(float2*)(Cg + (size_t)row * N + col)       = make_float2(c[0] * scale, c[1] * scale);
                *(float2*)(Cg + (size_t)(row + 8) * N + col) = make_float2(c[2] * scale, c[3] * scale);
            } else {
                float* Cg = (float*)Cout + (size_t)b * M * N;
                *(float2*)(Cg + (size_t)row * N + col)       = make_float2(c[0], c[1]);
                *(float2*)(Cg + (size_t)(row + 8) * N + col) = make_float2(c[2], c[3]);
            }
        }
    }
}

// =====================================================================
// elementwise fp32 -> fp16 conversion (rn)
// =====================================================================
__global__ __launch_bounds__(256) void to_f16(const float* __restrict__ in,
                                              __half* __restrict__ out, int n4)
{
    int i = blockIdx.x * blockDim.x + threadIdx.x;
    if (i < n4) {
        float4 v = ((const float4*)in)[i];
        __half2 h0 = __floats2half2_rn(v.x, v.y);
        __half2 h1 = __floats2half2_rn(v.z, v.w);
        ((__half2*)out)[2 * i]     = h0;
        ((__half2*)out)[2 * i + 1] = h1;
    }
}

// =====================================================================
// Causal softmax: reads fp32 scores (j<=i), writes fp16 probs + fp16 zero tail.
// One CTA (256 thr) per row.
// =====================================================================
__global__ __launch_bounds__(256) void softmax_causal(const float* __restrict__ Pg,
                                                      __half* __restrict__ Ph)
{
    const int i = blockIdx.x;
    const int b = blockIdx.y;
    const float* row = Pg + ((size_t)b * SEQ + i) * SEQ;
    __half* prow = Ph + ((size_t)b * SEQ + i) * SEQ;
    const int len = i + 1;
    const int len4 = len >> 2;

    __shared__ __align__(16) float buf[SEQ];
    __shared__ float red[8];
    __shared__ float sval;

    const int tid = threadIdx.x;
    const int lane = tid & 31;
    const int warp = tid >> 5;

    // ---- pass 1: load + max ----
    float m = -1e30f;
    for (int j4 = tid; j4 < len4; j4 += 256) {
        float4 v = ((const float4*)row)[j4];
        ((float4*)buf)[j4] = v;
        m = fmaxf(fmaxf(fmaxf(m, v.x), fmaxf(v.y, v.z)), v.w);
    }
    for (int j = len4 * 4 + tid; j < len; j += 256) {
        float v = row[j];
        buf[j] = v;
        m = fmaxf(m, v);
    }
#pragma unroll
    for (int o = 16; o > 0; o >>= 1) m = fmaxf(m, __shfl_xor_sync(0xffffffffu, m, o));
    if (lane == 0) red[warp] = m;
    __syncthreads();
    if (tid == 0) {
        float mm = red[0];
#pragma unroll
        for (int w = 1; w < 8; w++) mm = fmaxf(mm, red[w]);
        sval = mm;
    }
    __syncthreads();
    const float rowmax = sval;
    __syncthreads();

    // ---- pass 2: exp + sum ----
    float s = 0.0f;
    for (int j4 = tid; j4 < len4; j4 += 256) {
        float4 v = ((const float4*)buf)[j4];
        v.x = __expf(v.x - rowmax);
        v.y = __expf(v.y - rowmax);
        v.z = __expf(v.z - rowmax);
        v.w = __expf(v.w - rowmax);
        ((float4*)buf)[j4] = v;
        s += v.x + v.y + v.z + v.w;
    }
    for (int j = len4 * 4 + tid; j < len; j += 256) {
        float e = __expf(buf[j] - rowmax);
        buf[j] = e;
        s += e;
    }
#pragma unroll
    for (int o = 16; o > 0; o >>= 1) s += __shfl_xor_sync(0xffffffffu, s, o);
    if (lane == 0) red[warp] = s;
    __syncthreads();
    if (tid == 0) {
        float ss = red[0];
#pragma unroll
        for (int w = 1; w < 8; w++) ss += red[w];
        sval = 1.0f / ss;
    }
    __syncthreads();
    const float inv = sval;

    // ---- pass 3: write fp16 probs + zero tail ----
    for (int j4 = tid; j4 < len4; j4 += 256) {
        float4 v = ((const float4*)buf)[j4];
        __half2 h0 = __floats2half2_rn(v.x * inv, v.y * inv);
        __half2 h1 = __floats2half2_rn(v.z * inv, v.w * inv);
        ((__half2*)prow)[2 * j4]     = h0;
        ((__half2*)prow)[2 * j4 + 1] = h1;
    }
    for (int j = len4 * 4 + tid; j < len; j += 256)
        prow[j] = __float2half_rn(buf[j] * inv);
    for (int j = len + tid; j < SEQ; j += 256)
        prow[j] = __float2half_rn(0.0f);
}

// =====================================================================
// launch
// =====================================================================
extern "C" void kernel_launch(void* const* d_in, const int* in_sizes, int n_in,
                              void* d_out, int out_size)
{
    const float* x  = (const float*)d_in[0];
    const float* Wq = (const float*)d_in[1];
    const float* bq = (const float*)d_in[2];
    const float* Wk = (const float*)d_in[3];
    const float* bk = (const float*)d_in[4];
    const float* Wv = (const float*)d_in[5];
    const float* bv = (const float*)d_in[6];
    float* out = (float*)d_out;

    __half* q;  cudaGetSymbolAddress((void**)&q,  g_q);
    __half* k;  cudaGetSymbolAddress((void**)&k,  g_k);
    __half* v;  cudaGetSymbolAddress((void**)&v,  g_v);
    float*  p;  cudaGetSymbolAddress((void**)&p,  g_p);
    __half* ph; cudaGetSymbolAddress((void**)&ph, g_ph);
    __half* xh; cudaGetSymbolAddress((void**)&xh, g_xh);
    __half* wh; cudaGetSymbolAddress((void**)&wh, g_wh);

    // 0) convert x and weights to fp16
    {
        int n4x = MTOT * EMB / 4;
        to_f16<<<(n4x + 255) / 256, 256>>>(x, xh, n4x);
        int n4w = EMB * EMB / 4;
        to_f16<<<(n4w + 255) / 256, 256>>>(Wq, wh + (size_t)0 * EMB * EMB, n4w);
        to_f16<<<(n4w + 255) / 256, 256>>>(Wk, wh + (size_t)1 * EMB * EMB, n4w);
        to_f16<<<(n4w + 255) / 256, 256>>>(Wv, wh + (size_t)2 * EMB * EMB, n4w);
    }

    // 1) QKV projections (V transposed -> Vt[b][e][s])
    dim3 gProj(EMB / 128, MTOT / 128, 1);
    mma_gemm<0><<<gProj, 256>>>(xh, wh + (size_t)0 * EMB * EMB, bq, q, MTOT, EMB, EMB, 1.0f);
    mma_gemm<0><<<gProj, 256>>>(xh, wh + (size_t)1 * EMB * EMB, bk, k, MTOT, EMB, EMB, 1.0f);
    mma_gemm<1><<<gProj, 256>>>(xh, wh + (size_t)2 * EMB * EMB, bv, v, MTOT, EMB, EMB, 1.0f);

    // 2) scaled QK^T -> fp32 scores (causal tile skip; garbage above diag never read)
    dim3 gQK(SEQ / 128, SEQ / 128, BATCH);
    mma_gemm<2><<<gQK, 256>>>(q, k, nullptr, p, SEQ, SEQ, EMB, 1.0f / 32.0f);

    // 3) causal softmax: fp32 scores -> fp16 probs (zeros above diagonal)
    dim3 gSM(SEQ, BATCH, 1);
    softmax_causal<<<gSM, 256>>>(p, ph);

    // 4) PV: O = P * Vt^T (fp16 x fp16 -> fp32), k truncated at diagonal
    dim3 gPV(EMB / 128, SEQ / 128, BATCH);
    mma_gemm<3><<<gPV, 256>>>(ph, v, nullptr, out, SEQ, EMB, SEQ, 1.0f);
}